// round 15
// baseline (speedup 1.0000x reference)
#include <cuda_runtime.h>
#include <cuda_bf16.h>
#include <cstdint>

// LocallyConnected1d via TF32 mma.sync + cp.async (all plain sm_80 PTX).
// out[b,c,o] = sum_{ci,k} x[b,ci,4o+k] * w[c,ci,o,k] / 8
// One CTA per o: D[128,64] = A[128,512] @ B[64,512]^T  (K = ci*8)
// R15: 3-stage cp.async ring, 2 groups in flight, ONE __syncthreads per tile.

#define CIN     64
#define COUT    64
#define OUT_DIM 256
#define KW      8
#define L_DIM   1028

#define NTHREADS 256        // 8 warps: 4 along M x 2 along N, warp tile 32x32
#define KBLK     32         // fp32 K per tile (4 ci x 8 taps)
#define NBLK     16         // 512 / 32
#define NSTAGE   3

// padded rows: 32 data words + 4 pad = 36 words = 144B (16B-aligned, LDS conflict-free)
#define ROW_B    144
#define A_BYTES  (128 * ROW_B)   // 18432
#define B_BYTES  (64 * ROW_B)    // 9216
#define STAGE_BYTES (A_BYTES + B_BYTES)       // 27648
#define SMEM_TOTAL  (NSTAGE * STAGE_BYTES)    // 82944 -> still 2 CTAs/SM

__device__ __forceinline__ uint32_t smem_u32(const void* p) {
    uint32_t a;
    asm("{ .reg .u64 t; cvta.to.shared.u64 t, %1; cvt.u32.u64 %0, t; }" : "=r"(a) : "l"(p));
    return a;
}

__device__ __forceinline__ uint32_t lds_tf32(uint32_t addr) {
    float f;
    asm("ld.shared.f32 %0, [%1];" : "=f"(f) : "r"(addr));
    uint32_t t;
    asm("cvt.rna.tf32.f32 %0, %1;" : "=r"(t) : "f"(f));
    return t;
}

__device__ __forceinline__ void mma_tf32(float* d, const uint32_t* a, const uint32_t* b) {
    asm volatile(
        "mma.sync.aligned.m16n8k8.row.col.f32.tf32.tf32.f32 "
        "{%0,%1,%2,%3}, {%4,%5,%6,%7}, {%8,%9}, {%0,%1,%2,%3};"
        : "+f"(d[0]), "+f"(d[1]), "+f"(d[2]), "+f"(d[3])
        : "r"(a[0]), "r"(a[1]), "r"(a[2]), "r"(a[3]), "r"(b[0]), "r"(b[1]));
}

__device__ __forceinline__ void cp16(uint32_t dst, const void* src) {
    asm volatile("cp.async.cg.shared.global [%0], [%1], 16;" :: "r"(dst), "l"(src));
}

__global__ void __launch_bounds__(NTHREADS, 2)
lc1d_tf32(const float* __restrict__ x,
          const float* __restrict__ w,
          float* __restrict__ out)
{
    extern __shared__ char smem[];
    const uint32_t sbase = smem_u32(smem);
    const int tid = threadIdx.x;
    const int wid = tid >> 5;
    const int lid = tid & 31;
    const int o   = blockIdx.x;
    const int xcol = 4 * o;

    // mma geometry: 4 m-warps x 2 n-warps, warp tile 32x32
    const int m0 = (wid >> 1) * 32;
    const int n0 = (wid & 1) * 32;
    const int g  = lid >> 2;          // 0..7
    const int tq = lid & 3;           // 0..3

    float acc[2][4][4];
    #pragma unroll
    for (int i = 0; i < 2; i++)
        #pragma unroll
        for (int j = 0; j < 4; j++)
            #pragma unroll
            for (int q = 0; q < 4; q++)
                acc[i][j][q] = 0.0f;

    // ---- cp.async stage issue: tile t (ci in [4t, 4t+4)) into stage buffer ----
    #define CP_ISSUE(t, buf)                                                   \
        do {                                                                   \
            const int cib = (t) * 4;                                           \
            const uint32_t sb = sbase + (uint32_t)(buf) * STAGE_BYTES;         \
            _Pragma("unroll")                                                  \
            for (int i = 0; i < 4; i++) {          /* A: 1024 x 16B */         \
                int idx  = i * 256 + tid;                                      \
                int m    = idx >> 3;                                           \
                int ci   = (idx >> 1) & 3;                                     \
                int half = idx & 1;                                            \
                cp16(sb + m * ROW_B + ci * 32 + half * 16,                     \
                     &x[(m * CIN + cib + ci) * L_DIM + xcol + half * 4]);      \
            }                                                                  \
            _Pragma("unroll")                                                  \
            for (int i = 0; i < 2; i++) {          /* B: 512 x 16B */          \
                int idx  = i * 256 + tid;                                      \
                int c    = idx >> 3;                                           \
                int ci   = (idx >> 1) & 3;                                     \
                int half = idx & 1;                                            \
                cp16(sb + A_BYTES + c * ROW_B + ci * 32 + half * 16,           \
                     &w[((c * CIN + cib + ci) * OUT_DIM + o) * KW + half * 4]);\
            }                                                                  \
            asm volatile("cp.async.commit_group;" ::: "memory");               \
        } while (0)

    // prologue: 2 stages in flight
    CP_ISSUE(0, 0);
    CP_ISSUE(1, 1);

    int buf_c = 0;                    // t % 3
    int buf_n = 2;                    // (t+2) % 3

    for (int t = 0; t < NBLK; t++) {
        if (t < NBLK - 1)
            asm volatile("cp.async.wait_group 1;" ::: "memory");
        else
            asm volatile("cp.async.wait_group 0;" ::: "memory");
        __syncthreads();              // ONE barrier per tile

        // issue t+2 into the buffer that held t-1 (drained: all warps passed
        // the barrier above only after finishing compute of t-1 last iter)
        if (t + 2 < NBLK) CP_ISSUE(t + 2, buf_n);

        const uint32_t ab = sbase + (uint32_t)buf_c * STAGE_BYTES;
        const uint32_t bb = ab + A_BYTES;

        #pragma unroll
        for (int ks = 0; ks < 4; ks++) {
            const int kb = ks * 8;
            uint32_t Af[2][4], Bf[4][2];

            #pragma unroll
            for (int mi = 0; mi < 2; mi++) {
                uint32_t base = ab + (m0 + mi * 16 + g) * ROW_B + (kb + tq) * 4;
                Af[mi][0] = lds_tf32(base);
                Af[mi][1] = lds_tf32(base + 8 * ROW_B);
                Af[mi][2] = lds_tf32(base + 16);
                Af[mi][3] = lds_tf32(base + 8 * ROW_B + 16);
            }
            #pragma unroll
            for (int nj = 0; nj < 4; nj++) {
                uint32_t base = bb + (n0 + nj * 8 + g) * ROW_B + (kb + tq) * 4;
                Bf[nj][0] = lds_tf32(base);
                Bf[nj][1] = lds_tf32(base + 16);
            }

            #pragma unroll
            for (int mi = 0; mi < 2; mi++)
                #pragma unroll
                for (int nj = 0; nj < 4; nj++)
                    mma_tf32(acc[mi][nj], Af[mi], Bf[nj]);
        }

        buf_c = (buf_c == NSTAGE - 1) ? 0 : buf_c + 1;
        buf_n = (buf_n == NSTAGE - 1) ? 0 : buf_n + 1;
    }

    // ---- epilogue: out[b, c, o] = acc / 8 ----
    const float s = 0.125f;
    #pragma unroll
    for (int mi = 0; mi < 2; mi++) {
        #pragma unroll
        for (int nj = 0; nj < 4; nj++) {
            int r0 = m0 + mi * 16 + g;
            int c0 = n0 + nj * 8 + 2 * tq;
            out[((r0    ) * COUT + c0    ) * OUT_DIM + o] = acc[mi][nj][0] * s;
            out[((r0    ) * COUT + c0 + 1) * OUT_DIM + o] = acc[mi][nj][1] * s;
            out[((r0 + 8) * COUT + c0    ) * OUT_DIM + o] = acc[mi][nj][2] * s;
            out[((r0 + 8) * COUT + c0 + 1) * OUT_DIM + o] = acc[mi][nj][3] * s;
        }
    }
}

extern "C" void kernel_launch(void* const* d_in, const int* in_sizes, int n_in,
                              void* d_out, int out_size)
{
    const float* x = (const float*)d_in[0];   // [128, 64, 1028]
    const float* w = (const float*)d_in[1];   // [1, 64, 64, 256, 8]
    float* out = (float*)d_out;               // [128, 64, 256]
    (void)in_sizes; (void)n_in; (void)out_size;

    cudaFuncSetAttribute(lc1d_tf32, cudaFuncAttributeMaxDynamicSharedMemorySize,
                         SMEM_TOTAL);
    lc1d_tf32<<<OUT_DIM, NTHREADS, SMEM_TOTAL>>>(x, w, out);
}

// round 17
// speedup vs baseline: 1.0763x; 1.0763x over previous
#include <cuda_runtime.h>
#include <cuda_bf16.h>
#include <cstdint>

// LocallyConnected1d via TF32 mma.sync + cp.async (plain sm_80 PTX).
// out[b,c,o] = sum_{ci,k} x[b,ci,4o+k] * w[c,ci,o,k] / 8
// One CTA per o: D[128,64] = A[128,512] @ B[64,512]^T  (K = ci*8)
// R16: k-relabeled slices -> LDS.128 fragment loads (4 slices per load),
//      1-bit XOR row swizzle (conflict-free, no padding), 3-stage cp.async ring.

#define CIN     64
#define COUT    64
#define OUT_DIM 256
#define KW      8
#define L_DIM   1028

#define NTHREADS 256        // 8 warps: 4 along M x 2 along N, warp tile 32x32
#define NBLK     16         // 512 / 32 fp32-K per tile
#define NSTAGE   3

#define ROW_B    128        // 32 fp32 words per row, no pad (XOR swizzle instead)
#define A_BYTES  (128 * ROW_B)   // 16384
#define B_BYTES  (64 * ROW_B)    // 8192
#define STAGE_BYTES (A_BYTES + B_BYTES)       // 24576
#define SMEM_TOTAL  (NSTAGE * STAGE_BYTES)    // 73728 -> 2 CTAs/SM

__device__ __forceinline__ uint32_t smem_u32(const void* p) {
    uint32_t a;
    asm("{ .reg .u64 t; cvta.to.shared.u64 t, %1; cvt.u32.u64 %0, t; }" : "=r"(a) : "l"(p));
    return a;
}

__device__ __forceinline__ void lds128f(float* f, uint32_t addr) {
    asm volatile("ld.shared.v4.f32 {%0,%1,%2,%3}, [%4];"
                 : "=f"(f[0]), "=f"(f[1]), "=f"(f[2]), "=f"(f[3]) : "r"(addr));
}

__device__ __forceinline__ uint32_t tf32(float f) {
    uint32_t t;
    asm("cvt.rna.tf32.f32 %0, %1;" : "=r"(t) : "f"(f));
    return t;
}

__device__ __forceinline__ void mma_tf32(float* d, const uint32_t* a, const uint32_t* b) {
    asm volatile(
        "mma.sync.aligned.m16n8k8.row.col.f32.tf32.tf32.f32 "
        "{%0,%1,%2,%3}, {%4,%5,%6,%7}, {%8,%9}, {%0,%1,%2,%3};"
        : "+f"(d[0]), "+f"(d[1]), "+f"(d[2]), "+f"(d[3])
        : "r"(a[0]), "r"(a[1]), "r"(a[2]), "r"(a[3]), "r"(b[0]), "r"(b[1]));
}

__device__ __forceinline__ void cp16(uint32_t dst, const void* src) {
    asm volatile("cp.async.cg.shared.global [%0], [%1], 16;" :: "r"(dst), "l"(src));
}

__global__ void __launch_bounds__(NTHREADS, 2)
lc1d_tf32(const float* __restrict__ x,
          const float* __restrict__ w,
          float* __restrict__ out)
{
    extern __shared__ char smem[];
    const uint32_t sbase = smem_u32(smem);
    const int tid = threadIdx.x;
    const int wid = tid >> 5;
    const int lid = tid & 31;
    const int o   = blockIdx.x;
    const int xcol = 4 * o;

    // mma geometry: 4 m-warps x 2 n-warps, warp tile 32x32
    const int m0 = (wid >> 1) * 32;
    const int n0 = (wid & 1) * 32;
    const int g  = lid >> 2;          // 0..7
    const int tq = lid & 3;           // 0..3

    // fragment byte offsets within a row (XOR swizzle by row parity = g&1)
    const uint32_t sw     = (uint32_t)((g & 1) << 6);       // 16 words = 64B
    const uint32_t off_lo = ((uint32_t)(tq << 4)) ^ sw;     // words 4tq..4tq+3
    const uint32_t off_hi = ((uint32_t)(64 + (tq << 4))) ^ sw; // words 16+4tq..

    float acc[2][4][4];
    #pragma unroll
    for (int i = 0; i < 2; i++)
        #pragma unroll
        for (int j = 0; j < 4; j++)
            #pragma unroll
            for (int q = 0; q < 4; q++)
                acc[i][j][q] = 0.0f;

    // ---- cp.async stage issue: tile t (ci in [4t, 4t+4)) into stage buffer ----
    // 16B chunk c of row r stored at chunk position c ^ ((r&1)<<2).
    #define CP_ISSUE(t, buf)                                                   \
        do {                                                                   \
            const int cib = (t) * 4;                                           \
            const uint32_t sb = sbase + (uint32_t)(buf) * STAGE_BYTES;         \
            _Pragma("unroll")                                                  \
            for (int i = 0; i < 4; i++) {          /* A: 1024 x 16B */         \
                int idx  = i * 256 + tid;                                      \
                int m    = idx >> 3;                                           \
                int ch   = idx & 7;                                            \
                int ci   = ch >> 1;                                            \
                int half = ch & 1;                                             \
                cp16(sb + m * ROW_B + ((ch ^ ((m & 1) << 2)) << 4),            \
                     &x[(m * CIN + cib + ci) * L_DIM + xcol + half * 4]);      \
            }                                                                  \
            _Pragma("unroll")                                                  \
            for (int i = 0; i < 2; i++) {          /* B: 512 x 16B */          \
                int idx  = i * 256 + tid;                                      \
                int c    = idx >> 3;                                           \
                int ch   = idx & 7;                                            \
                int ci   = ch >> 1;                                            \
                int half = ch & 1;                                             \
                cp16(sb + A_BYTES + c * ROW_B + ((ch ^ ((c & 1) << 2)) << 4),  \
                     &w[((c * CIN + cib + ci) * OUT_DIM + o) * KW + half * 4]);\
            }                                                                  \
            asm volatile("cp.async.commit_group;" ::: "memory");               \
        } while (0)

    // prologue: 2 stages in flight
    CP_ISSUE(0, 0);
    CP_ISSUE(1, 1);

    int buf_c = 0;                    // t % 3
    int buf_n = 2;                    // (t+2) % 3

    for (int t = 0; t < NBLK; t++) {
        if (t < NBLK - 1)
            asm volatile("cp.async.wait_group 1;" ::: "memory");
        else
            asm volatile("cp.async.wait_group 0;" ::: "memory");
        __syncthreads();

        if (t + 2 < NBLK) CP_ISSUE(t + 2, buf_n);

        const uint32_t ab = sbase + (uint32_t)buf_c * STAGE_BYTES;
        const uint32_t bb = ab + A_BYTES;

        // ---- fragment loads: 16 independent LDS.128 (each -> 4 slices) ----
        float Afv[2][4][4];   // [mi][areg][slice]
        float Bfv[4][2][4];   // [nj][breg][slice]

        #pragma unroll
        for (int mi = 0; mi < 2; mi++) {
            uint32_t r0 = ab + (uint32_t)(m0 + mi * 16 + g) * ROW_B;
            uint32_t r1 = r0 + 8 * ROW_B;
            lds128f(Afv[mi][0], r0 + off_lo);
            lds128f(Afv[mi][1], r1 + off_lo);
            lds128f(Afv[mi][2], r0 + off_hi);
            lds128f(Afv[mi][3], r1 + off_hi);
        }
        #pragma unroll
        for (int nj = 0; nj < 4; nj++) {
            uint32_t rn = bb + (uint32_t)(n0 + nj * 8 + g) * ROW_B;
            lds128f(Bfv[nj][0], rn + off_lo);
            lds128f(Bfv[nj][1], rn + off_hi);
        }

        // ---- cvt + 4 MMA slices ----
        #pragma unroll
        for (int j = 0; j < 4; j++) {
            uint32_t At[2][4], Bt[4][2];
            #pragma unroll
            for (int mi = 0; mi < 2; mi++) {
                At[mi][0] = tf32(Afv[mi][0][j]);
                At[mi][1] = tf32(Afv[mi][1][j]);
                At[mi][2] = tf32(Afv[mi][2][j]);
                At[mi][3] = tf32(Afv[mi][3][j]);
            }
            #pragma unroll
            for (int nj = 0; nj < 4; nj++) {
                Bt[nj][0] = tf32(Bfv[nj][0][j]);
                Bt[nj][1] = tf32(Bfv[nj][1][j]);
            }
            #pragma unroll
            for (int mi = 0; mi < 2; mi++)
                #pragma unroll
                for (int nj = 0; nj < 4; nj++)
                    mma_tf32(acc[mi][nj], At[mi], Bt[nj]);
        }

        buf_c = (buf_c == NSTAGE - 1) ? 0 : buf_c + 1;
        buf_n = (buf_n == NSTAGE - 1) ? 0 : buf_n + 1;
    }

    // ---- epilogue: out[b, c, o] = acc / 8 ----
    const float s = 0.125f;
    #pragma unroll
    for (int mi = 0; mi < 2; mi++) {
        #pragma unroll
        for (int nj = 0; nj < 4; nj++) {
            int r0 = m0 + mi * 16 + g;
            int c0 = n0 + nj * 8 + 2 * tq;
            out[((r0    ) * COUT + c0    ) * OUT_DIM + o] = acc[mi][nj][0] * s;
            out[((r0    ) * COUT + c0 + 1) * OUT_DIM + o] = acc[mi][nj][1] * s;
            out[((r0 + 8) * COUT + c0    ) * OUT_DIM + o] = acc[mi][nj][2] * s;
            out[((r0 + 8) * COUT + c0 + 1) * OUT_DIM + o] = acc[mi][nj][3] * s;
        }
    }
}

extern "C" void kernel_launch(void* const* d_in, const int* in_sizes, int n_in,
                              void* d_out, int out_size)
{
    const float* x = (const float*)d_in[0];   // [128, 64, 1028]
    const float* w = (const float*)d_in[1];   // [1, 64, 64, 256, 8]
    float* out = (float*)d_out;               // [128, 64, 256]
    (void)in_sizes; (void)n_in; (void)out_size;

    cudaFuncSetAttribute(lc1d_tf32, cudaFuncAttributeMaxDynamicSharedMemorySize,
                         SMEM_TOTAL);
    lc1d_tf32<<<OUT_DIM, NTHREADS, SMEM_TOTAL>>>(x, w, out);
}